// round 15
// baseline (speedup 1.0000x reference)
#include <cuda_runtime.h>
#include <cuda_fp16.h>
#include <cstdint>
#include <math.h>

#define TT 128
#define BB 32
#define HH 256
#define II 256
#define G4 1024   // 4*H
#define CL 4      // CTAs per cluster
#define NTH 512
#define JS 64     // j-slice per rank (HH/CL)

// ---- SMEM layout sizes (floats) — single source of truth ------------------
#define SZ_MBAR    8
#define SZ_WAZ     16384   // W_a slice fp16 (32768 halves = 64 KB)
#define SZ_WHHS    28672   // W_hh resident fp16: 7168 uint4 = 112 KB
#define SZ_ZBUF    4096    // z history fp16: 128 x 64 halves
#define SZ_BUF     4096    // h history fp16: 128 x 64 halves
#define SZ_SCP     512
#define SZ_ALPHA   128
#define SZ_HFULLH  128     // h_full fp16: 256 halves
#define SZ_HUFULLH 128     // hu_full fp16: 256 halves
#define SZ_Y1PART  512
#define SZ_YHLOC   64
#define SZ_XPS     256
#define SZ_SCSTG   128
#define SZ_HLOCH   32      // h_loc fp16: 64 halves
#define SZ_CLOC    64
#define SZ_BAS     64
#define SZ_GPART   512
#define SMEM_FLOATS (SZ_MBAR + SZ_WAZ + SZ_WHHS + SZ_ZBUF + SZ_BUF + SZ_SCP \
                   + SZ_ALPHA + SZ_HFULLH + SZ_HUFULLH + SZ_Y1PART + SZ_YHLOC \
                   + SZ_XPS + SZ_SCSTG + SZ_HLOCH + SZ_CLOC + SZ_BAS + SZ_GPART)
// = 55784 floats = 223,136 B  (< 227 KB cap)

// Scratch: hoisted input projection xproj[t][b][row]
__device__ float g_xproj[(size_t)TT * BB * G4];       // 16 MB
// fp16 W_hh, permuted per rank into two k-halves (see whh16_kernel)
__device__ __half g_whh16[CL * 2 * 16 * 256 * 8];     // 512 KB

// ---------------------------------------------------------------------------
// Kernel A: xproj = emb @ W_ih^T + (b_ih + b_hh)   (M=4096, N=1024, K=256)
// ---------------------------------------------------------------------------
__global__ void __launch_bounds__(256) xproj_kernel(
    const float* __restrict__ emb, const float* __restrict__ W_ih,
    const float* __restrict__ b_ih, const float* __restrict__ b_hh)
{
    __shared__ float As[64][65];
    __shared__ float Bs[64][65];
    const int K = II;
    const int bm = blockIdx.x * 64, bn = blockIdx.y * 64;
    const int tx = threadIdx.x & 15, ty = threadIdx.x >> 4;
    float acc[4][4] = {};

    for (int k0 = 0; k0 < K; k0 += 64) {
        for (int i = threadIdx.x; i < 64 * 64; i += 256) {
            int r = i >> 6, cc = i & 63;
            As[r][cc] = emb[(size_t)(bm + r) * K + k0 + cc];
            Bs[r][cc] = W_ih[(size_t)(bn + r) * K + k0 + cc];
        }
        __syncthreads();
        #pragma unroll
        for (int k = 0; k < 64; k++) {
            float a[4], bv[4];
            #pragma unroll
            for (int i = 0; i < 4; i++) a[i] = As[ty * 4 + i][k];
            #pragma unroll
            for (int j = 0; j < 4; j++) bv[j] = Bs[tx * 4 + j][k];
            #pragma unroll
            for (int i = 0; i < 4; i++)
                #pragma unroll
                for (int j = 0; j < 4; j++)
                    acc[i][j] += a[i] * bv[j];
        }
        __syncthreads();
    }
    #pragma unroll
    for (int i = 0; i < 4; i++)
        #pragma unroll
        for (int j = 0; j < 4; j++) {
            int r = bm + ty * 4 + i, cI = bn + tx * 4 + j;
            g_xproj[(size_t)r * G4 + cI] = acc[i][j] + b_ih[cI] + b_hh[cI];
        }
}

// ---------------------------------------------------------------------------
// Kernel A2: convert + permute W_hh into g_whh16 (two k-halves per rank)
// ---------------------------------------------------------------------------
__global__ void __launch_bounds__(256) whh16_kernel(const float* __restrict__ W_hh)
{
    int idx = blockIdx.x * 256 + threadIdx.x;        // 262144 total halves
    int e    = idx & 7;
    int row  = (idx >> 3) & 255;
    int i    = (idx >> 11) & 15;
    int part = (idx >> 15) & 1;
    int rr   = idx >> 16;
    int grow = (row >> 6) * 256 + 64 * rr + (row & 63);
    int k    = part * 128 + i * 8 + e;
    g_whh16[idx] = __float2half_rn(W_hh[(size_t)grow * HH + k]);
}

// ---------------------------------------------------------------------------
// DSMEM / mbarrier helpers (vectorized stores, no atomics)
// ---------------------------------------------------------------------------
__device__ __forceinline__ uint32_t smem_u32(const void* p) {
    return (uint32_t)__cvta_generic_to_shared(p);
}
__device__ __forceinline__ uint32_t my_rank() {
    uint32_t r;
    asm("mov.u32 %0, %%cluster_ctarank;" : "=r"(r));
    return r;
}
__device__ __forceinline__ void st_cluster4(uint32_t laddr, int rank, float4 v) {
    uint32_t ra;
    asm volatile("mapa.shared::cluster.u32 %0, %1, %2;" : "=r"(ra) : "r"(laddr), "r"(rank));
    asm volatile("st.shared::cluster.v4.f32 [%0], {%1,%2,%3,%4};"
                 :: "r"(ra), "f"(v.x), "f"(v.y), "f"(v.z), "f"(v.w) : "memory");
}
__device__ __forceinline__ void st_cluster2(uint32_t laddr, int rank, uint2 v) {
    uint32_t ra;
    asm volatile("mapa.shared::cluster.u32 %0, %1, %2;" : "=r"(ra) : "r"(laddr), "r"(rank));
    asm volatile("st.shared::cluster.v2.b32 [%0], {%1,%2};"
                 :: "r"(ra), "r"(v.x), "r"(v.y) : "memory");
}
__device__ __forceinline__ void bar_arrive_rank(uint32_t lbar, int rank) {
    uint32_t ra;
    asm volatile("mapa.shared::cluster.u32 %0, %1, %2;" : "=r"(ra) : "r"(lbar), "r"(rank));
    asm volatile("mbarrier.arrive.release.cluster.shared::cluster.b64 _, [%0];"
                 :: "r"(ra) : "memory");
}
__device__ __forceinline__ void bar_wait(uint32_t lbar, uint32_t parity) {
    asm volatile(
        "{\n\t.reg .pred P;\n\t"
        "LW_%=:\n\t"
        "mbarrier.try_wait.parity.acquire.cluster.shared::cta.b64 P, [%0], %1, 0x989680;\n\t"
        "@P bra LD_%=;\n\t"
        "bra LW_%=;\n\t"
        "LD_%=:\n\t}"
        :: "r"(lbar), "r"(parity) : "memory");
}

// dot of 8 fp16 x 8 fp16 (uint4 each), half2 accumulate, fp32 result
__device__ __forceinline__ float dot8hh(uint4 w, uint4 x) {
    const __half2* hw = reinterpret_cast<const __half2*>(&w);
    const __half2* hx = reinterpret_cast<const __half2*>(&x);
    __half2 a = __hmul2(hw[0], hx[0]);
    a = __hfma2(hw[1], hx[1], a);
    a = __hfma2(hw[2], hx[2], a);
    a = __hfma2(hw[3], hx[3], a);
    float2 f = __half22float2(a);
    return f.x + f.y;
}

// fast tanh via MUFU exp: (e^{2x}-1)/(e^{2x}+1), clamped to avoid inf/inf
__device__ __forceinline__ float tanh_fast(float x) {
    x = fminf(fmaxf(x, -15.f), 15.f);
    float e = __expf(2.f * x);
    return __fdividef(e - 1.f, e + 1.f);
}

// ---------------------------------------------------------------------------
// Kernel B: 4-CTA cluster per batch element (32 clusters = 128 CTAs).
// Pipelined step: scores(t+1) + h push + B0 arrive fused into the tail of
// step t, right after the cell. Unnormalized softmax (inv folded into hu).
// 2 cluster barriers/step; fp16 HFMA2 GEMVs; W_hh 112 KB resident.
// ---------------------------------------------------------------------------
__global__ void __launch_bounds__(NTH, 1) __cluster_dims__(CL, 1, 1)
recur_kernel(
    const int*   __restrict__ lens,
    const float* __restrict__ W_a,    // [256, 512]
    const float* __restrict__ b_a,    // [256]
    float* __restrict__ out)          // output[T,B,H] ++ h_fin[B,H] ++ c_fin[B,H]
{
    extern __shared__ float smf[];
    unsigned long long* mbar = (unsigned long long*)smf;   // 2 barriers (smf[0..3])
    float* s_inv   = smf + 6;              // softmax 1/sum (spare slot in mbar pad)
    float* waZ_f   = smf      + SZ_MBAR;
    float* whhS_f  = waZ_f    + SZ_WAZ;
    float* zbuf_f  = whhS_f   + SZ_WHHS;
    float* buf_f   = zbuf_f   + SZ_ZBUF;
    float* scp     = buf_f    + SZ_BUF;
    float* alpha   = scp      + SZ_SCP;    // stores UNNORMALIZED e_s
    float* hfull_f = alpha    + SZ_ALPHA;
    float* hufull_f= hfull_f  + SZ_HFULLH;
    float* y1part  = hufull_f + SZ_HUFULLH;
    float* yH_loc  = y1part   + SZ_Y1PART;
    float* xps     = yH_loc   + SZ_YHLOC;
    float* scstage = xps      + SZ_XPS;
    float* hloc_f  = scstage  + SZ_SCSTG;
    float* c_loc   = hloc_f   + SZ_HLOCH;
    float* ba_s    = c_loc    + SZ_CLOC;
    float* gpart   = ba_s     + SZ_BAS;   // SZ_GPART floats; ends at SMEM_FLOATS

    __half* waH      = (__half*)waZ_f;
    uint4*  waU      = (uint4*)waZ_f;
    uint4*  whhS     = (uint4*)whhS_f;     // [0..4095]: k0-127; [4096..7167]: k128-223
    __half* zbuf_h   = (__half*)zbuf_f;
    __half* buf_h    = (__half*)buf_f;
    uint4*  buf_u4   = (uint4*)buf_f;      // buf_u4[s*8 + L] = halves k=L*8..L*8+7
    __half* hfull_h  = (__half*)hfull_f;
    uint4*  hfull_u4 = (uint4*)hfull_f;    // 32 uint4
    __half* hufull_h = (__half*)hufull_f;
    uint4*  hufull_u4= (uint4*)hufull_f;   // 32 uint4
    __half* hloc_h   = (__half*)hloc_f;    // 64 halves
    uint4*  hloc_u4  = (uint4*)hloc_f;     // 8 uint4

    const int tid  = threadIdx.x;
    const int warp = tid >> 5, lane = tid & 31;
    const int r    = (int)my_rank();
    const int b    = blockIdx.x / CL;
    const int myLen = lens[b];

    const uint32_t bar0 = smem_u32(&mbar[0]);
    const uint32_t bar1 = smem_u32(&mbar[1]);

    // ---- one-time: W_a rows [64r,64r+64) -> fp16 SMEM [hs][k8][row][e] ----
    for (int idx = tid; idx < 32768; idx += NTH) {
        int e = idx & 7, row = (idx >> 3) & 63, k8 = (idx >> 9) & 31, hs = idx >> 14;
        int col = hs * 256 + k8 * 8 + e;
        waH[idx] = __float2half_rn(W_a[(size_t)(JS * r + row) * 512 + col]);
    }
    // ---- one-time: W_hh resident parts -> SMEM (7168 uint4 = 112 KB) ----
    {
        const uint4* src0 = (const uint4*)g_whh16 + (r * 2 + 0) * 4096;
        const uint4* src1 = (const uint4*)g_whh16 + (r * 2 + 1) * 4096;
        for (int i = tid; i < 4096; i += NTH) whhS[i] = __ldcg(&src0[i]);
        for (int i = tid; i < 3072; i += NTH) whhS[4096 + i] = __ldcg(&src1[i]);
    }
    if (tid < JS) ba_s[tid] = __ldg(&b_a[JS * r + tid]);
    if (tid < 256) { hufull_h[tid] = __half(0.f); hfull_h[tid] = __half(0.f); }
    if (tid < 64) { hloc_h[tid] = __half(0.f); c_loc[tid] = 0.f; }
    if (tid == 0) {
        #pragma unroll
        for (int k = 0; k < 2; k++)
            asm volatile("mbarrier.init.shared.b64 [%0], %1;"
                         :: "r"(smem_u32(&mbar[k])), "r"(CL) : "memory");
        asm volatile("fence.mbarrier_init.release.cluster;" ::: "memory");
    }
    __syncthreads();
    asm volatile("barrier.cluster.arrive.aligned;" ::: "memory");
    asm volatile("barrier.cluster.wait.aligned;" ::: "memory");

    // prologue: B0 completion #0 (nothing to push for t=0)
    if (tid < CL) bar_arrive_rank(bar0, tid);

    // streamed W_hh k[224:256) (part1, i=12..15): row = tid&255
    const uint4* WpHi = (const uint4*)g_whh16 + (r * 2 + 1) * 4096 + (tid & 255);

    for (int t = 0; t < TT; t++) {
        const uint32_t par = (uint32_t)(t & 1);

        // ======== wait B0 (h(t-1) + score partials for t pushed in prev tail)
        if (warp == 0) bar_wait(bar0, par);
        __syncthreads();

        // stage xproj (long-latency LDG, consumed at cell)
        if (tid < 256) {
            int grow = (tid >> 6) * 256 + JS * r + (tid & 63);
            xps[tid] = __ldg(&g_xproj[((size_t)t * BB + b) * G4 + grow]);
        }

        // ======== P2: [softmax warp0] || [local z/yH GEMV]; y1; hu; push ====
        if (t > 0) {
            {   // local GEMV: 512 thr = 64 rows x (2 hs x 4 chunks), fp16 x
                int row = tid & 63, cg = tid >> 6;   // cg: hs=cg>>2, c=cg&3
                int hs = cg >> 2, c = cg & 3;
                float acc = 0.f;
                #pragma unroll
                for (int i = 0; i < 8; i++) {
                    int k8 = c * 8 + i;
                    acc += dot8hh(waU[hs * 2048 + k8 * 64 + row], hfull_u4[k8]);
                }
                gpart[cg * 64 + row] = acc;
            }
            if (warp == 0) {  // unnormalized softmax: alpha[s]=e_s, s_inv=1/sum
                float v[4];
                float m = -1e30f;
                #pragma unroll
                for (int c = 0; c < 4; c++) {
                    int s = lane + 32 * c;
                    float sum = -1e30f;
                    if (s < t)
                        sum = scp[0 * 128 + s] + scp[1 * 128 + s]
                            + scp[2 * 128 + s] + scp[3 * 128 + s];
                    v[c] = sum;
                    m = fmaxf(m, sum);
                }
                #pragma unroll
                for (int o = 16; o > 0; o >>= 1) m = fmaxf(m, __shfl_xor_sync(0xffffffffu, m, o));
                float tot = 0.f;
                #pragma unroll
                for (int c = 0; c < 4; c++) {
                    int s = lane + 32 * c;
                    if (s < t) { v[c] = __expf(v[c] - m); alpha[s] = v[c]; tot += v[c]; }
                }
                #pragma unroll
                for (int o = 16; o > 0; o >>= 1) tot += __shfl_xor_sync(0xffffffffu, tot, o);
                if (lane == 0) *s_inv = 1.f / tot;
            }
            __syncthreads();

            // reduce GEMV partials (128 thr) + y1 over s<t-1 (all 512 thr)
            if (tid < 128) {
                int hs = tid >> 6, row = tid & 63;
                float v = gpart[(hs * 4 + 0) * 64 + row] + gpart[(hs * 4 + 1) * 64 + row]
                        + gpart[(hs * 4 + 2) * 64 + row] + gpart[(hs * 4 + 3) * 64 + row];
                if (hs == 0) zbuf_h[(t - 1) * 64 + row] = __float2half_rn(v);
                else         yH_loc[row] = v;
            }
            {   // y1 partials over old history only (unnormalized e)
                int g = tid >> 6, row = tid & 63;
                float acc = 0.f;
                for (int s = g; s < t - 1; s += 8)
                    acc += alpha[s] * __half2float(zbuf_h[s * 64 + row]);
                y1part[g * 64 + row] = acc;
            }
            __syncthreads();

            if (tid < 16) {   // hu rows (4 per thread) -> fp16, push u64 x4
                float hv[4];
                float aT  = alpha[t - 1];
                float inv = *s_inv;
                #pragma unroll
                for (int rr = 0; rr < 4; rr++) {
                    int row = tid * 4 + rr;
                    float ya = y1part[0 * 64 + row] + y1part[1 * 64 + row]
                             + y1part[2 * 64 + row] + y1part[3 * 64 + row]
                             + y1part[4 * 64 + row] + y1part[5 * 64 + row]
                             + y1part[6 * 64 + row] + y1part[7 * 64 + row]
                             + aT * __half2float(zbuf_h[(t - 1) * 64 + row]);
                    hv[rr] = tanh_fast(ya * inv + yH_loc[row] + ba_s[row]);
                }
                __half2 p01 = __floats2half2_rn(hv[0], hv[1]);
                __half2 p23 = __floats2half2_rn(hv[2], hv[3]);
                uint2 pkt;
                pkt.x = *reinterpret_cast<uint32_t*>(&p01);
                pkt.y = *reinterpret_cast<uint32_t*>(&p23);
                #pragma unroll
                for (int dest = 0; dest < CL; dest++)
                    st_cluster2(smem_u32(&hufull_h[JS * r + tid * 4]), dest, pkt);
            }
        }
        if (tid < CL) bar_arrive_rank(bar1, tid);
        if (warp == 0) bar_wait(bar1, par);                           // B1
        __syncthreads();

        // ======== P3: gates GEMV (fp16 HFMA2); 112KB resident, 16KB stream ==
        {
            int hs = tid >> 8, row = tid & 255;
            const uint4* x4 = hufull_u4 + hs * 16;
            float acc = 0.f;
            if (hs == 0) {
                const uint4* W = whhS + row;          // k[0:128)
                #pragma unroll
                for (int i = 0; i < 16; i++)
                    acc += dot8hh(W[i * 256], x4[i]);
            } else {
                const uint4* W = whhS + 4096 + row;   // k[128:224) resident
                #pragma unroll
                for (int i = 0; i < 12; i++)
                    acc += dot8hh(W[i * 256], x4[i]);
                #pragma unroll
                for (int i = 12; i < 16; i++)         // k[224:256) streamed
                    acc += dot8hh(__ldcg(WpHi + i * 256), x4[i]);
            }
            gpart[tid] = acc;
        }
        __syncthreads();

        // ======== fused gates-sum + cell update on my j-slice ===============
        if (tid < JS) {
            int j = JS * r + tid;
            float gv[4];
            #pragma unroll
            for (int g = 0; g < 4; g++) {
                int row = g * 64 + tid;
                gv[g] = gpart[row] + gpart[256 + row] + xps[row];
            }
            float si = 1.f / (1.f + __expf(-gv[0]));
            float sf = 1.f / (1.f + __expf(-gv[1]));
            float so = 1.f / (1.f + __expf(-gv[3]));
            float cn = sf * c_loc[tid] + si * tanh_fast(gv[2]);
            float hn = so * tanh_fast(cn);
            c_loc[tid] = cn;
            __half hn_h = __float2half_rn(hn);
            hloc_h[tid] = hn_h;
            buf_h[t * 64 + tid] = hn_h;

            out[((size_t)t * BB + b) * HH + j] = hn;
            if (t == myLen - 1) {
                out[(size_t)TT * BB * HH + (size_t)b * HH + j] = hn;
                out[(size_t)TT * BB * HH + (size_t)BB * HH + (size_t)b * HH + j] = cn;
            }
        }
        __syncthreads();

        // ======== TAIL: scores for t+1 (local) + h push; then score push ====
        if (t < TT - 1) {
            const int tn = t + 1;
            for (int blk = warp; blk * 4 < tn; blk += 16) {
                int g = lane >> 3, L = lane & 7;
                int s = blk * 4 + g;
                float acc = 0.f;
                if (s < tn) acc = dot8hh(buf_u4[s * 8 + L], hloc_u4[L]);
                acc += __shfl_xor_sync(0xffffffffu, acc, 1);
                acc += __shfl_xor_sync(0xffffffffu, acc, 2);
                acc += __shfl_xor_sync(0xffffffffu, acc, 4);
                if (L == 0 && s < tn) scstage[s] = acc;
            }
            if (tid < 32) {               // h(t) halves -> h_full on all ranks
                int dest = tid >> 3, q = tid & 7;
                st_cluster4(smem_u32(&hfull_h[JS * r + q * 8]), dest,
                            *(const float4*)&hloc_h[q * 8]);
            }
            __syncthreads();
            if (tid < 128) {              // score partials -> all ranks
                int chunk = tid >> 2, peer = tid & 3;
                if (chunk * 4 < tn)
                    st_cluster4(smem_u32(&scp[r * 128 + chunk * 4]), peer,
                                *(const float4*)&scstage[chunk * 4]);
            }
            if (tid < CL) bar_arrive_rank(bar0, tid);
        }
    }
}

// ---------------------------------------------------------------------------
extern "C" void kernel_launch(void* const* d_in, const int* in_sizes, int n_in,
                              void* d_out, int out_size)
{
    const float* embs = (const float*)d_in[0];
    const int*   lens = (const int*)  d_in[1];
    const float* W_ih = (const float*)d_in[2];
    const float* W_hh = (const float*)d_in[3];
    const float* b_ih = (const float*)d_in[4];
    const float* b_hh = (const float*)d_in[5];
    const float* W_a  = (const float*)d_in[6];
    const float* b_a  = (const float*)d_in[7];
    float* out = (float*)d_out;

    const int smem_bytes = SMEM_FLOATS * (int)sizeof(float);   // 223,136 B
    cudaFuncSetAttribute(recur_kernel, cudaFuncAttributeMaxDynamicSharedMemorySize, smem_bytes);

    whh16_kernel<<<1024, 256>>>(W_hh);
    xproj_kernel<<<dim3((TT * BB) / 64, G4 / 64), 256>>>(embs, W_ih, b_ih, b_hh);
    recur_kernel<<<BB * CL, NTH, smem_bytes>>>(lens, W_a, b_a, out);
}